// round 1
// baseline (speedup 1.0000x reference)
#include <cuda_runtime.h>

#define NB 16
#define NT 2048
#define ND 512

// ---------------- scratch (device globals; no allocation allowed) ----------
__device__ __align__(16) float g_w0[ND];      // conv tap 0
__device__ __align__(16) float g_w1[ND];      // conv tap 1 + 1.0 (residual folded)
__device__ __align__(16) float g_w2[ND];      // conv tap 2
__device__ __align__(16) float g_aT[NT * NB]; // alphas transposed [t][b]
__device__ __align__(16) float g_Wt[NB * NT]; // per-step weight (cur)
__device__ __align__(16) float g_Rem[NB * NT];// rem at fire steps
__device__ int g_firepos[NB * NT];            // fire timestep per (b, rank)
__device__ int g_nf[NB];                      // fire count per batch

// ---------------- kernel W: transpose conv weights, fold residual ----------
__global__ void prep_weights_kernel(const float* __restrict__ conv_w) {
    int d = blockIdx.x * blockDim.x + threadIdx.x;
    if (d < ND) {
        g_w0[d] = conv_w[d * 3 + 0];
        g_w1[d] = conv_w[d * 3 + 1] + 1.0f;  // mem + ctx residual folded into tap 1
        g_w2[d] = conv_w[d * 3 + 2];
    }
}

// ---------------- kernel A: alphas = sigmoid(lin(relu(dwconv+ctx))) --------
// Block = 256 threads (8 warps), covers 32 consecutive t of one batch.
// Warp w handles t = t0 + 4w + i (i=0..3); lane covers d = 4*lane + 128*j.
// 3-tap rows reused via L1 (34 rows x 2KB = 68KB working set per block).
__global__ __launch_bounds__(256, 2)
void alphas_kernel(const float* __restrict__ hidden,
                   const float* __restrict__ conv_b,
                   const float* __restrict__ lin_w,
                   const float* __restrict__ lin_b,
                   float* __restrict__ alphas) {
    const int b     = blockIdx.y;
    const int t0    = blockIdx.x * 32;
    const int warp  = threadIdx.x >> 5;
    const int lane  = threadIdx.x & 31;
    const int tbase = t0 + warp * 4;
    const float* hb = hidden + (size_t)b * NT * ND;

    float acc0 = 0.f, acc1 = 0.f, acc2 = 0.f, acc3 = 0.f;

#pragma unroll
    for (int j = 0; j < 4; j++) {
        const int d = lane * 4 + j * 128;
        const float4 w0 = *reinterpret_cast<const float4*>(&g_w0[d]);
        const float4 w1 = *reinterpret_cast<const float4*>(&g_w1[d]);
        const float4 w2 = *reinterpret_cast<const float4*>(&g_w2[d]);
        const float4 cb = *reinterpret_cast<const float4*>(&conv_b[d]);
        const float4 lw = *reinterpret_cast<const float4*>(&lin_w[d]);

#pragma unroll
        for (int i = 0; i < 4; i++) {
            const int t = tbase + i;
            const float* hrow = hb + (size_t)t * ND + d;
            const float4 hc = *reinterpret_cast<const float4*>(hrow);
            float4 hm = make_float4(0.f, 0.f, 0.f, 0.f);
            float4 hp = make_float4(0.f, 0.f, 0.f, 0.f);
            if (t > 0)      hm = *reinterpret_cast<const float4*>(hrow - ND);
            if (t < NT - 1) hp = *reinterpret_cast<const float4*>(hrow + ND);

            float a = 0.f, v;
            v = fmaf(hm.x, w0.x, fmaf(hc.x, w1.x, fmaf(hp.x, w2.x, cb.x)));
            a = fmaf(fmaxf(v, 0.f), lw.x, a);
            v = fmaf(hm.y, w0.y, fmaf(hc.y, w1.y, fmaf(hp.y, w2.y, cb.y)));
            a = fmaf(fmaxf(v, 0.f), lw.y, a);
            v = fmaf(hm.z, w0.z, fmaf(hc.z, w1.z, fmaf(hp.z, w2.z, cb.z)));
            a = fmaf(fmaxf(v, 0.f), lw.z, a);
            v = fmaf(hm.w, w0.w, fmaf(hc.w, w1.w, fmaf(hp.w, w2.w, cb.w)));
            a = fmaf(fmaxf(v, 0.f), lw.w, a);

            if (i == 0) acc0 += a;
            else if (i == 1) acc1 += a;
            else if (i == 2) acc2 += a;
            else acc3 += a;
        }
    }

    const float lb = __ldg(lin_b);
    float accs[4] = {acc0, acc1, acc2, acc3};
#pragma unroll
    for (int i = 0; i < 4; i++) {
        float a = accs[i];
#pragma unroll
        for (int o = 16; o > 0; o >>= 1) a += __shfl_xor_sync(0xffffffffu, a, o);
        if (lane == 0) {
            const float logit = a + lb;
            alphas[b * NT + tbase + i] = 1.0f / (1.0f + __expf(-logit));
        }
    }
}

// ---------------- kernel B: bit-exact sequential CIF scan ------------------
// One block. Phase 1: all 512 threads transpose alphas -> [t][b] so the 16
// scan threads read one 64B sector per step. Phase 2: thread b runs the
// sequential recurrence in the reference's exact float order.
__global__ void scan_kernel(const float* __restrict__ alphas,
                            float* __restrict__ fires,
                            float* __restrict__ token_num) {
    for (int idx = threadIdx.x; idx < NB * NT; idx += blockDim.x) {
        const int b = idx >> 11;        // / NT
        const int t = idx & (NT - 1);   // % NT
        g_aT[t * NB + b] = alphas[idx];
    }
    __syncthreads();
    if (threadIdx.x >= NB) return;

    const int b = threadIdx.x;
    float integ = 0.f, tn = 0.f;
    int nf = 0;
    float* fb = fires + b * NT;
    float* wb = g_Wt + b * NT;
    float* rb = g_Rem + b * NT;
    int*   fp = g_firepos + b * NT;

#pragma unroll 8
    for (int t = 0; t < NT; t++) {
        const float a    = g_aT[t * NB + b];
        const float dist = 1.0f - integ;             // off-chain
        const float s    = integ + a;                // chain: FADD
        const bool fire  = (s >= 1.0f);              // chain: FSETP (pred-as-data)
        const float cur  = fire ? dist : a;          // off-chain
        fb[t] = s;                                   // pre-reset fire value (output)
        wb[t] = cur;
        rb[t] = a - cur;                             // rem (only meaningful at fires)
        fp[nf] = t;                                  // branch-free: overwritten until fire
        nf += fire ? 1 : 0;
        tn += a;                                     // independent chain
        integ = fire ? (s - 1.0f) : s;               // chain: FSEL (−1 exact, s∈[1,2))
    }
    g_nf[b] = nf;
    token_num[b] = tn;
}

// ---------------- kernel C: parallel segmented gather ----------------------
// acoustic[b,r,:] = rem(prev_fire)*h[prev_fire] + sum_{t in (prev,cur]} w_t*h_t
// One tiny block per (b, r); segments avg ~2 timesteps; h likely L2-resident.
__global__ void gather_kernel(const float* __restrict__ hidden,
                              float* __restrict__ acoustic, int ML) {
    const int r = blockIdx.x;
    const int b = blockIdx.y;
    const int d = threadIdx.x * 4;

    float4 acc = make_float4(0.f, 0.f, 0.f, 0.f);
    if (r < g_nf[b]) {
        const float* hb = hidden + (size_t)b * NT * ND + d;
        const int end = g_firepos[b * NT + r];
        int start = 0;
        if (r > 0) {
            const int ps    = g_firepos[b * NT + r - 1];
            const float rem = g_Rem[b * NT + ps];
            const float4 h  = *reinterpret_cast<const float4*>(hb + (size_t)ps * ND);
            acc.x = rem * h.x; acc.y = rem * h.y;
            acc.z = rem * h.z; acc.w = rem * h.w;
            start = ps + 1;
        }
        for (int t = start; t <= end; t++) {
            const float w  = g_Wt[b * NT + t];   // uniform broadcast load
            const float4 h = *reinterpret_cast<const float4*>(hb + (size_t)t * ND);
            acc.x = fmaf(w, h.x, acc.x); acc.y = fmaf(w, h.y, acc.y);
            acc.z = fmaf(w, h.z, acc.z); acc.w = fmaf(w, h.w, acc.w);
        }
    }
    // r >= nf -> zeros (reference zero-pads); also overwrites 0xAA poison.
    *reinterpret_cast<float4*>(&acoustic[((size_t)b * ML + r) * ND + d]) = acc;
}

// ---------------- launch ----------------------------------------------------
extern "C" void kernel_launch(void* const* d_in, const int* in_sizes, int n_in,
                              void* d_out, int out_size) {
    const float* hidden = (const float*)d_in[0];
    const float* conv_w = (const float*)d_in[1];
    const float* conv_b = (const float*)d_in[2];
    const float* lin_w  = (const float*)d_in[3];
    const float* lin_b  = (const float*)d_in[4];
    float* out = (float*)d_out;

    // out = concat(acoustic[B,ML,D], token_num[B], alphas[B,T], fires[B,T])
    const int ML = (out_size - NB - 2 * NB * NT) / (NB * ND);
    float* acoustic  = out;
    float* token_num = out + (size_t)NB * ML * ND;
    float* alphas    = token_num + NB;
    float* fires     = alphas + NB * NT;

    prep_weights_kernel<<<(ND + 127) / 128, 128>>>(conv_w);
    alphas_kernel<<<dim3(NT / 32, NB), 256>>>(hidden, conv_b, lin_w, lin_b, alphas);
    scan_kernel<<<1, 512>>>(alphas, fires, token_num);
    if (ML > 0) gather_kernel<<<dim3(ML, NB), ND / 4>>>(hidden, acoustic, ML);
}

// round 2
// speedup vs baseline: 3.5205x; 3.5205x over previous
#include <cuda_runtime.h>

#define NB 16
#define NT 2048
#define ND 512

// ---------------- scratch (device globals; no allocation allowed) ----------
__device__ __align__(16) float g_w0[ND];        // conv tap 0
__device__ __align__(16) float g_w1[ND];        // conv tap 1 + 1.0 (residual folded)
__device__ __align__(16) float g_w2[ND];        // conv tap 2
__device__ __align__(16) float g_aT4[NT * NB];  // alphas, layout [t/4][b][4]
__device__ __align__(16) float g_Wt[NB * NT];   // per-step weight (cur), exact
__device__ __align__(16) float2 g_fire[NB * NT];// per fire: (t as int bits, rem)
__device__ int g_nf[NB];                        // fire count per batch

// ---------------- kernel W: transpose conv weights, fold residual ----------
__global__ void prep_weights_kernel(const float* __restrict__ conv_w) {
    int d = blockIdx.x * blockDim.x + threadIdx.x;
    if (d < ND) {
        g_w0[d] = conv_w[d * 3 + 0];
        g_w1[d] = conv_w[d * 3 + 1] + 1.0f;  // residual folded into tap 1
        g_w2[d] = conv_w[d * 3 + 2];
    }
}

// ---------------- kernel A: alphas = sigmoid(lin(relu(dwconv+ctx))) --------
// Block = 256 threads (8 warps), covers 32 consecutive t of one batch.
// Warp w handles t = t0 + 4w + i (i=0..3); lane covers d = 4*lane + 128*j.
// Lane 0 writes 4 alphas as one float4 to BOTH the output and g_aT4
// (layout [t/4][b][4]) for the scan's vectorized pipelined loads.
__global__ __launch_bounds__(256, 2)
void alphas_kernel(const float* __restrict__ hidden,
                   const float* __restrict__ conv_b,
                   const float* __restrict__ lin_w,
                   const float* __restrict__ lin_b,
                   float* __restrict__ alphas) {
    const int b     = blockIdx.y;
    const int t0    = blockIdx.x * 32;
    const int warp  = threadIdx.x >> 5;
    const int lane  = threadIdx.x & 31;
    const int tbase = t0 + warp * 4;
    const float* hb = hidden + (size_t)b * NT * ND;

    float acc0 = 0.f, acc1 = 0.f, acc2 = 0.f, acc3 = 0.f;

#pragma unroll
    for (int j = 0; j < 4; j++) {
        const int d = lane * 4 + j * 128;
        const float4 w0 = *reinterpret_cast<const float4*>(&g_w0[d]);
        const float4 w1 = *reinterpret_cast<const float4*>(&g_w1[d]);
        const float4 w2 = *reinterpret_cast<const float4*>(&g_w2[d]);
        const float4 cb = *reinterpret_cast<const float4*>(&conv_b[d]);
        const float4 lw = *reinterpret_cast<const float4*>(&lin_w[d]);

#pragma unroll
        for (int i = 0; i < 4; i++) {
            const int t = tbase + i;
            const float* hrow = hb + (size_t)t * ND + d;
            const float4 hc = *reinterpret_cast<const float4*>(hrow);
            float4 hm = make_float4(0.f, 0.f, 0.f, 0.f);
            float4 hp = make_float4(0.f, 0.f, 0.f, 0.f);
            if (t > 0)      hm = *reinterpret_cast<const float4*>(hrow - ND);
            if (t < NT - 1) hp = *reinterpret_cast<const float4*>(hrow + ND);

            float a = 0.f, v;
            v = fmaf(hm.x, w0.x, fmaf(hc.x, w1.x, fmaf(hp.x, w2.x, cb.x)));
            a = fmaf(fmaxf(v, 0.f), lw.x, a);
            v = fmaf(hm.y, w0.y, fmaf(hc.y, w1.y, fmaf(hp.y, w2.y, cb.y)));
            a = fmaf(fmaxf(v, 0.f), lw.y, a);
            v = fmaf(hm.z, w0.z, fmaf(hc.z, w1.z, fmaf(hp.z, w2.z, cb.z)));
            a = fmaf(fmaxf(v, 0.f), lw.z, a);
            v = fmaf(hm.w, w0.w, fmaf(hc.w, w1.w, fmaf(hp.w, w2.w, cb.w)));
            a = fmaf(fmaxf(v, 0.f), lw.w, a);

            if (i == 0) acc0 += a;
            else if (i == 1) acc1 += a;
            else if (i == 2) acc2 += a;
            else acc3 += a;
        }
    }

    const float lb = __ldg(lin_b);
    float accs[4] = {acc0, acc1, acc2, acc3};
    float4 av;
#pragma unroll
    for (int i = 0; i < 4; i++) {
        float a = accs[i];
#pragma unroll
        for (int o = 16; o > 0; o >>= 1) a += __shfl_xor_sync(0xffffffffu, a, o);
        ((float*)&av)[i] = 1.0f / (1.0f + __expf(-(a + lb)));
    }
    if (lane == 0) {
        *reinterpret_cast<float4*>(&alphas[b * NT + tbase]) = av;
        *reinterpret_cast<float4*>(&g_aT4[((tbase >> 2) * NB + b) * 4]) = av;
    }
}

// ---------------- kernel B: bit-exact sequential CIF scan ------------------
// One warp; thread b runs the sequential recurrence in the reference's exact
// float order. Alpha loads are double-buffered 32-step register tiles
// (LDG.128 x 8 per tile, issued a full tile ahead) so no latency sits on the
// integ dependency chain. Outputs: fires (float4-buffered), g_Wt (exact cur,
// float4-buffered), g_fire (packed (t, rem) per fire, predicated STG.64).
__global__ void scan_kernel(float* __restrict__ fires,
                            float* __restrict__ token_num) {
    const int b = threadIdx.x;
    if (b >= NB) return;

    const float4* ap = reinterpret_cast<const float4*>(g_aT4) + b;  // [g*NB + b]

    float4 buf_cur[8], buf_nxt[8];
#pragma unroll
    for (int k = 0; k < 8; k++) buf_cur[k] = ap[k * NB];

    float integ = 0.f, tn = 0.f;
    int nf = 0;
    float*  fb = fires + b * NT;
    float*  wb = g_Wt + b * NT;
    float2* pb = g_fire + b * NT;

    for (int t0 = 0; t0 < NT; t0 += 32) {
        if (t0 + 32 < NT) {
#pragma unroll
            for (int k = 0; k < 8; k++) buf_nxt[k] = ap[((t0 >> 2) + 8 + k) * NB];
        }
#pragma unroll
        for (int k = 0; k < 8; k++) {
            float a4[4] = {buf_cur[k].x, buf_cur[k].y, buf_cur[k].z, buf_cur[k].w};
            float4 fout, wout;
#pragma unroll
            for (int i = 0; i < 4; i++) {
                const float a    = a4[i];
                const float dist = 1.0f - integ;            // off-chain
                const float s    = integ + a;               // chain: FADD
                const bool fire  = (s >= 1.0f);             // chain: FSETP
                const float cur  = fire ? dist : a;         // off-chain FSEL
                ((float*)&fout)[i] = s;                     // pre-reset fire value
                ((float*)&wout)[i] = cur;
                const float rem = a - cur;                  // exact (same op as ref)
                const float2 pk = make_float2(__int_as_float(t0 + k * 4 + i), rem);
                if (fire) pb[nf] = pk;                      // single predicated STG.64
                nf += fire ? 1 : 0;
                tn += a;                                    // independent chain
                integ = fire ? (s - 1.0f) : s;              // chain: FSEL (exact -1)
            }
            const int t = t0 + k * 4;
            *reinterpret_cast<float4*>(fb + t) = fout;
            *reinterpret_cast<float4*>(wb + t) = wout;
        }
#pragma unroll
        for (int k = 0; k < 8; k++) buf_cur[k] = buf_nxt[k];
    }
    g_nf[b] = nf;
    token_num[b] = tn;
}

// ---------------- kernel C: parallel segmented gather ----------------------
// acoustic[b,r,:] = rem(prev_fire)*h[prev_fire] + sum_{t in (prev,cur]} w_t*h_t
// One block per (b, r); segments avg ~2 timesteps; hidden mostly L2-resident.
__global__ void gather_kernel(const float* __restrict__ hidden,
                              float* __restrict__ acoustic, int ML) {
    const int r = blockIdx.x;
    const int b = blockIdx.y;
    const int d = threadIdx.x * 4;

    float4 acc = make_float4(0.f, 0.f, 0.f, 0.f);
    if (r < g_nf[b]) {
        const float* hb = hidden + (size_t)b * NT * ND + d;
        const float2 fc = g_fire[b * NT + r];
        const int end   = __float_as_int(fc.x);
        int start = 0;
        if (r > 0) {
            const float2 fp = g_fire[b * NT + r - 1];
            const int ps    = __float_as_int(fp.x);
            const float rem = fp.y;
            const float4 h  = *reinterpret_cast<const float4*>(hb + (size_t)ps * ND);
            acc.x = rem * h.x; acc.y = rem * h.y;
            acc.z = rem * h.z; acc.w = rem * h.w;
            start = ps + 1;
        }
        for (int t = start; t <= end; t++) {
            const float w  = g_Wt[b * NT + t];   // uniform broadcast load (exact cur)
            const float4 h = *reinterpret_cast<const float4*>(hb + (size_t)t * ND);
            acc.x = fmaf(w, h.x, acc.x); acc.y = fmaf(w, h.y, acc.y);
            acc.z = fmaf(w, h.z, acc.z); acc.w = fmaf(w, h.w, acc.w);
        }
    }
    // r >= nf -> zeros (reference zero-pads); also overwrites 0xAA poison.
    *reinterpret_cast<float4*>(&acoustic[((size_t)b * ML + r) * ND + d]) = acc;
}

// ---------------- launch ----------------------------------------------------
extern "C" void kernel_launch(void* const* d_in, const int* in_sizes, int n_in,
                              void* d_out, int out_size) {
    const float* hidden = (const float*)d_in[0];
    const float* conv_w = (const float*)d_in[1];
    const float* conv_b = (const float*)d_in[2];
    const float* lin_w  = (const float*)d_in[3];
    const float* lin_b  = (const float*)d_in[4];
    float* out = (float*)d_out;

    // out = concat(acoustic[B,ML,D], token_num[B], alphas[B,T], fires[B,T])
    const int ML = (out_size - NB - 2 * NB * NT) / (NB * ND);
    float* acoustic  = out;
    float* token_num = out + (size_t)NB * ML * ND;
    float* alphas    = token_num + NB;
    float* fires     = alphas + NB * NT;

    prep_weights_kernel<<<(ND + 127) / 128, 128>>>(conv_w);
    alphas_kernel<<<dim3(NT / 32, NB), 256>>>(hidden, conv_b, lin_w, lin_b, alphas);
    scan_kernel<<<1, 32>>>(fires, token_num);
    if (ML > 0) gather_kernel<<<dim3(ML, NB), ND / 4>>>(hidden, acoustic, ML);
}

// round 3
// speedup vs baseline: 5.3468x; 1.5187x over previous
#include <cuda_runtime.h>

#define NB 16
#define NT 2048
#define ND 512
#define CH 32              // pass-2 chunk length (timesteps)
#define NCH (NT / CH)      // 64 chunks

// ---------------- scratch (device globals; no allocation allowed) ----------
__device__ __align__(16) float g_aT4[NT * NB];   // alphas, layout [t/4][b][4]
__device__ __align__(16) float g_Wt[NB * NT];    // per-step weight (cur), exact
__device__ __align__(16) float2 g_fire[NB * NT]; // per fire: (t as int bits, rem)
__device__ float g_integ0[NCH * NB];             // integ at chunk start
__device__ int   g_nf0[NCH * NB];                // fire count before chunk
__device__ int   g_nf[NB];                       // total fire count per batch

// ---------------- kernel A: alphas = sigmoid(lin(relu(dwconv+ctx))) --------
// Block = 256 threads (8 warps), covers 32 consecutive t of one batch.
// Warp w handles t = t0 + 4w + i (i=0..3); lane covers d = 4*lane + 128*j.
// Conv taps gathered directly from conv_w (K-interleaved); residual folded
// into tap 1. Lane 0 writes 4 alphas as one float4 to BOTH the output and
// g_aT4 (layout [t/4][b][4]) for the scan's vectorized pipelined loads.
__global__ __launch_bounds__(256, 2)
void alphas_kernel(const float* __restrict__ hidden,
                   const float* __restrict__ conv_w,
                   const float* __restrict__ conv_b,
                   const float* __restrict__ lin_w,
                   const float* __restrict__ lin_b,
                   float* __restrict__ alphas) {
    const int b     = blockIdx.y;
    const int t0    = blockIdx.x * 32;
    const int warp  = threadIdx.x >> 5;
    const int lane  = threadIdx.x & 31;
    const int tbase = t0 + warp * 4;
    const float* hb = hidden + (size_t)b * NT * ND;

    float acc0 = 0.f, acc1 = 0.f, acc2 = 0.f, acc3 = 0.f;

#pragma unroll
    for (int j = 0; j < 4; j++) {
        const int d = lane * 4 + j * 128;
        // 12 consecutive taps for d..d+3 (3 taps each), 48B aligned
        const float4 c0 = *reinterpret_cast<const float4*>(&conv_w[d * 3]);
        const float4 c1 = *reinterpret_cast<const float4*>(&conv_w[d * 3 + 4]);
        const float4 c2 = *reinterpret_cast<const float4*>(&conv_w[d * 3 + 8]);
        const float4 w0 = make_float4(c0.x, c0.w, c1.z, c2.y);
        const float4 w1 = make_float4(c0.y + 1.f, c1.x + 1.f, c1.w + 1.f, c2.z + 1.f);
        const float4 w2 = make_float4(c0.z, c1.y, c2.x, c2.w);
        const float4 cb = *reinterpret_cast<const float4*>(&conv_b[d]);
        const float4 lw = *reinterpret_cast<const float4*>(&lin_w[d]);

#pragma unroll
        for (int i = 0; i < 4; i++) {
            const int t = tbase + i;
            const float* hrow = hb + (size_t)t * ND + d;
            const float4 hc = *reinterpret_cast<const float4*>(hrow);
            float4 hm = make_float4(0.f, 0.f, 0.f, 0.f);
            float4 hp = make_float4(0.f, 0.f, 0.f, 0.f);
            if (t > 0)      hm = *reinterpret_cast<const float4*>(hrow - ND);
            if (t < NT - 1) hp = *reinterpret_cast<const float4*>(hrow + ND);

            float a = 0.f, v;
            v = fmaf(hm.x, w0.x, fmaf(hc.x, w1.x, fmaf(hp.x, w2.x, cb.x)));
            a = fmaf(fmaxf(v, 0.f), lw.x, a);
            v = fmaf(hm.y, w0.y, fmaf(hc.y, w1.y, fmaf(hp.y, w2.y, cb.y)));
            a = fmaf(fmaxf(v, 0.f), lw.y, a);
            v = fmaf(hm.z, w0.z, fmaf(hc.z, w1.z, fmaf(hp.z, w2.z, cb.z)));
            a = fmaf(fmaxf(v, 0.f), lw.z, a);
            v = fmaf(hm.w, w0.w, fmaf(hc.w, w1.w, fmaf(hp.w, w2.w, cb.w)));
            a = fmaf(fmaxf(v, 0.f), lw.w, a);

            if (i == 0) acc0 += a;
            else if (i == 1) acc1 += a;
            else if (i == 2) acc2 += a;
            else acc3 += a;
        }
    }

    const float lb = __ldg(lin_b);
    float accs[4] = {acc0, acc1, acc2, acc3};
    float4 av;
#pragma unroll
    for (int i = 0; i < 4; i++) {
        float a = accs[i];
#pragma unroll
        for (int o = 16; o > 0; o >>= 1) a += __shfl_xor_sync(0xffffffffu, a, o);
        ((float*)&av)[i] = 1.0f / (1.0f + __expf(-(a + lb)));
    }
    if (lane == 0) {
        *reinterpret_cast<float4*>(&alphas[b * NT + tbase]) = av;
        *reinterpret_cast<float4*>(&g_aT4[((tbase >> 2) * NB + b) * 4]) = av;
    }
}

// ---------------- kernel B1: minimal sequential chain (pass 1) -------------
// One warp; thread b runs the reference's exact recurrence with ONLY the
// integ/nf/tn state — no bulk stores on the warp. Snapshots (integ, nf) at
// every 32-step chunk boundary for pass 2 to replay in parallel.
// Chain/step: FADD(4) + FSETP->data(4) + FSEL(4) = 12 cyc; ~5 instr/step.
__global__ void scan_pass1(float* __restrict__ token_num) {
    const int b = threadIdx.x;
    if (b >= NB) return;

    const float4* ap = reinterpret_cast<const float4*>(g_aT4) + b;
    float4 buf_cur[8], buf_nxt[8];
#pragma unroll
    for (int k = 0; k < 8; k++) buf_cur[k] = ap[k * NB];

    float integ = 0.f, tn = 0.f;
    int nf = 0;

    for (int t0 = 0; t0 < NT; t0 += CH) {
        g_integ0[(t0 >> 5) * NB + b] = integ;   // chunk-boundary snapshot
        g_nf0[(t0 >> 5) * NB + b]   = nf;
        if (t0 + CH < NT) {
#pragma unroll
            for (int k = 0; k < 8; k++) buf_nxt[k] = ap[((t0 >> 2) + 8 + k) * NB];
        }
#pragma unroll
        for (int k = 0; k < 8; k++) {
            float a4[4] = {buf_cur[k].x, buf_cur[k].y, buf_cur[k].z, buf_cur[k].w};
#pragma unroll
            for (int i = 0; i < 4; i++) {
                const float a   = a4[i];
                const float s   = integ + a;          // chain: FADD
                const bool fire = (s >= 1.0f);        // chain: FSETP (as data)
                nf += fire ? 1 : 0;                   // off-chain
                tn += a;                              // off-chain
                integ = fire ? (s - 1.0f) : s;        // chain: FSEL
            }
        }
#pragma unroll
        for (int k = 0; k < 8; k++) buf_cur[k] = buf_nxt[k];
    }
    g_nf[b] = nf;
    token_num[b] = tn;
}

// ---------------- kernel B2: parallel chunk replay (pass 2) ----------------
// One block per 32-step chunk; thread b replays its chunk from the exact
// boundary state (identical float ops in identical order => bit-exact) and
// performs all bulk stores with full 64-SM parallelism.
__global__ void scan_pass2(float* __restrict__ fires) {
    const int c = blockIdx.x;
    const int b = threadIdx.x;
    if (b >= NB) return;

    float integ = g_integ0[c * NB + b];
    int nf      = g_nf0[c * NB + b];
    const int tbase = c * CH;
    const float4* ap = reinterpret_cast<const float4*>(g_aT4) + b;
    float*  fb = fires + b * NT;
    float*  wb = g_Wt + b * NT;
    float2* pb = g_fire + b * NT;

#pragma unroll
    for (int k = 0; k < 8; k++) {
        const float4 av = ap[((tbase >> 2) + k) * NB];
        float a4[4] = {av.x, av.y, av.z, av.w};
        float4 fout, wout;
#pragma unroll
        for (int i = 0; i < 4; i++) {
            const float a    = a4[i];
            const float dist = 1.0f - integ;
            const float s    = integ + a;
            const bool fire  = (s >= 1.0f);
            const float cur  = fire ? dist : a;
            ((float*)&fout)[i] = s;                  // pre-reset fire value
            ((float*)&wout)[i] = cur;
            const float rem = a - cur;               // exact (same op as ref)
            if (fire) pb[nf] = make_float2(__int_as_float(tbase + k * 4 + i), rem);
            nf += fire ? 1 : 0;
            integ = fire ? (s - 1.0f) : s;
        }
        const int t = tbase + k * 4;
        *reinterpret_cast<float4*>(fb + t) = fout;
        *reinterpret_cast<float4*>(wb + t) = wout;
    }
}

// ---------------- kernel C: parallel segmented gather ----------------------
// acoustic[b,r,:] = rem(prev_fire)*h[prev_fire] + sum_{t in (prev,cur]} w_t*h_t
// One block per (b, r); segments avg ~2 timesteps; hidden mostly L2-resident.
__global__ void gather_kernel(const float* __restrict__ hidden,
                              float* __restrict__ acoustic, int ML) {
    const int r = blockIdx.x;
    const int b = blockIdx.y;
    const int d = threadIdx.x * 4;

    float4 acc = make_float4(0.f, 0.f, 0.f, 0.f);
    if (r < g_nf[b]) {
        const float* hb = hidden + (size_t)b * NT * ND + d;
        const float2 fc = g_fire[b * NT + r];
        const int end   = __float_as_int(fc.x);
        int start = 0;
        if (r > 0) {
            const float2 fp = g_fire[b * NT + r - 1];
            const int ps    = __float_as_int(fp.x);
            const float rem = fp.y;
            const float4 h  = *reinterpret_cast<const float4*>(hb + (size_t)ps * ND);
            acc.x = rem * h.x; acc.y = rem * h.y;
            acc.z = rem * h.z; acc.w = rem * h.w;
            start = ps + 1;
        }
        for (int t = start; t <= end; t++) {
            const float w  = g_Wt[b * NT + t];   // uniform broadcast load (exact cur)
            const float4 h = *reinterpret_cast<const float4*>(hb + (size_t)t * ND);
            acc.x = fmaf(w, h.x, acc.x); acc.y = fmaf(w, h.y, acc.y);
            acc.z = fmaf(w, h.z, acc.z); acc.w = fmaf(w, h.w, acc.w);
        }
    }
    // r >= nf -> zeros (reference zero-pads); also overwrites 0xAA poison.
    *reinterpret_cast<float4*>(&acoustic[((size_t)b * ML + r) * ND + d]) = acc;
}

// ---------------- launch ----------------------------------------------------
extern "C" void kernel_launch(void* const* d_in, const int* in_sizes, int n_in,
                              void* d_out, int out_size) {
    const float* hidden = (const float*)d_in[0];
    const float* conv_w = (const float*)d_in[1];
    const float* conv_b = (const float*)d_in[2];
    const float* lin_w  = (const float*)d_in[3];
    const float* lin_b  = (const float*)d_in[4];
    float* out = (float*)d_out;

    // out = concat(acoustic[B,ML,D], token_num[B], alphas[B,T], fires[B,T])
    const int ML = (out_size - NB - 2 * NB * NT) / (NB * ND);
    float* acoustic  = out;
    float* token_num = out + (size_t)NB * ML * ND;
    float* alphas    = token_num + NB;
    float* fires     = alphas + NB * NT;

    alphas_kernel<<<dim3(NT / 32, NB), 256>>>(hidden, conv_w, conv_b, lin_w, lin_b, alphas);
    scan_pass1<<<1, 32>>>(token_num);
    scan_pass2<<<NCH, 32>>>(fires);
    if (ML > 0) gather_kernel<<<dim3(ML, NB), ND / 4>>>(hidden, acoustic, ML);
}